// round 16
// baseline (speedup 1.0000x reference)
#include <cuda_runtime.h>
#include <cuda_fp16.h>
#include <math.h>
#include <stdint.h>

#define BB 64
#define TT 2048
#define DD 256
#define NN (BB*TT)

#define MT 128                 // frames per CTA (16 CTAs per batch row)
#define KC 32                  // K chunk (fp16)
#define NCH (DD/KC)            // 8 chunks
#define NCTA (NN/MT)           // 1024
#define CPB (TT/MT)            // 16 chunks per batch

// ---------------- device scratch (no allocations allowed) ------------------
__device__ float g_part[NCTA * 2 * DD];   // per-tile [P_mu | P_m2]
__device__ float g_meta[NCTA * 2];        // per-tile [m_loc, Z_loc]
__device__ __align__(16) __half g_Wh[DD * DD];   // W rounded to fp16
__device__ int g_arr[BB];                 // per-batch arrival counts

// ---------------- smem layout (dynamic), bytes -----------------------------
#define SM_BIAS   0             // 256 f  (reused as mw scratch post-GEMM)
#define SM_ATTN   1024          // 256 f  (reused as zw scratch post-GEMM)
#define SM_RED    2048          // 512 f  (reused as p[] post-reduction)
#define SM_TILES  4096
#define A_STRIDE  80            // 32 fp16 padded: stride/16 odd -> ldmatrix conflict-free
#define OFF_ALO   10240         // lo plane within an A chunk region
#define A_CH_STRIDE 20544       // 20480 + 64 pad (stats LDS conflicts capped at 2-way)
#define SM_B      (SM_TILES + 8*A_CH_STRIDE)   // 168448
#define B_STG     20480
#define SMEM_BYTES (SM_B + 2*B_STG)            // 209408

// ---------------- PTX helpers (baseline ISA only: sm_80-class) -------------
__device__ __forceinline__ uint32_t smem_u32(const void* p) {
    uint32_t a;
    asm("{ .reg .u64 t; cvta.to.shared.u64 t, %1; cvt.u32.u64 %0, t; }" : "=r"(a) : "l"(p));
    return a;
}
__device__ __forceinline__ void ldsm4(uint32_t* r, uint32_t addr) {
    asm volatile("ldmatrix.sync.aligned.m8n8.x4.shared.b16 {%0,%1,%2,%3}, [%4];"
                 : "=r"(r[0]), "=r"(r[1]), "=r"(r[2]), "=r"(r[3]) : "r"(addr));
}
__device__ __forceinline__ void mma_f16(float* d, const uint32_t* a, const uint32_t* b) {
    asm volatile("mma.sync.aligned.m16n8k16.row.col.f32.f16.f16.f32 "
                 "{%0,%1,%2,%3}, {%4,%5,%6,%7}, {%8,%9}, {%0,%1,%2,%3};"
                 : "+f"(d[0]), "+f"(d[1]), "+f"(d[2]), "+f"(d[3])
                 : "r"(a[0]), "r"(a[1]), "r"(a[2]), "r"(a[3]), "r"(b[0]), "r"(b[1]));
}
#define CP16(dst, src) asm volatile("cp.async.cg.shared.global [%0], [%1], 16;" :: "r"(dst), "l"(src))
#define CP_COMMIT()    asm volatile("cp.async.commit_group;" ::: "memory")
#define CP_WAIT0()     asm volatile("cp.async.wait_group 0;" ::: "memory")

__device__ __forceinline__ uint32_t pk2h(float a, float b) {
    __half2 h = __floats2half2_rn(a, b);
    return *(uint32_t*)&h;
}

// ---------------------------------------------------------------------------
// Kernel 0: round W to fp16 + reset arrival counters.
// ---------------------------------------------------------------------------
__global__ void prep_kernel(const float* __restrict__ W)
{
    if (blockIdx.x == 0 && threadIdx.x < BB) g_arr[threadIdx.x] = 0;
    int i = blockIdx.x * blockDim.x + threadIdx.x;   // 16384 float4 units
    float4 w = ((const float4*)W)[i];
    uint2 hp;
    hp.x = pk2h(w.x, w.y);
    hp.y = pk2h(w.z, w.w);
    ((uint2*)g_Wh)[i] = hp;
}

// ---------------------------------------------------------------------------
// Kernel 1: fp16 2-term split GEMM on mma.sync (z = Ah*Wh + Al*Wh) + fused
// online-softmax stats + INLINE per-batch finalize by the last-arriving CTA
// (threadFenceReduction pattern). A chunks persist in smem; stats read x
// as hi+lo from smem. PREFIX-MASK SKIP for dead tiles.
// ---------------------------------------------------------------------------
__global__ __launch_bounds__(512, 1)
void score_kernel(const float* __restrict__ x, const int* __restrict__ mask,
                  const float* __restrict__ bias, const float* __restrict__ attn,
                  float* __restrict__ out)
{
    const long m0 = (long)blockIdx.x * MT;
    const int bidx = blockIdx.x / CPB;
    extern __shared__ char smem[];
    const uint32_t sb = smem_u32(smem);
    const int tid = threadIdx.x;
    int* s_flag = (int*)(smem + SM_RED + 2048);   // 4B scratch past red area

    if (mask[m0] != 0) {
        const int lane = tid & 31;
        const int wid = tid >> 5;
        const int wm = wid & 3;          // M quarter (32 rows)
        const int wn = wid >> 2;         // N quarter (64 cols)

        if (tid < 256) {
            ((float*)(smem + SM_BIAS))[tid] = bias[tid];
            ((float*)(smem + SM_ATTN))[tid] = attn[tid];
        }

        // ---- A global load / exact fp16 hi+lo split + store ----
        const int ar  = tid >> 3;        // row 0..63 (and +64)
        const int ag  = tid & 7;         // float4 group
        auto ldA = [&](int c, float4& v0, float4& v1) {
            const float* p = &x[(m0 + ar) * DD + c * KC + ag * 4];
            v0 = *(const float4*)p;
            v1 = *(const float4*)(p + 64 * DD);
        };
        auto stA = [&](float4 v0, float4 v1, int c) {
            char* stg = smem + SM_TILES + c * A_CH_STRIDE;
            uint32_t o = (uint32_t)(ar * A_STRIDE + ag * 8);
            uint2 h0, h1, l0, l1;
            __half a, b2;
            a = __float2half(v0.x); b2 = __float2half(v0.y);
            h0.x = pk2h(__half2float(a), __half2float(b2));
            l0.x = pk2h(v0.x - __half2float(a), v0.y - __half2float(b2));
            a = __float2half(v0.z); b2 = __float2half(v0.w);
            h0.y = pk2h(__half2float(a), __half2float(b2));
            l0.y = pk2h(v0.z - __half2float(a), v0.w - __half2float(b2));
            a = __float2half(v1.x); b2 = __float2half(v1.y);
            h1.x = pk2h(__half2float(a), __half2float(b2));
            l1.x = pk2h(v1.x - __half2float(a), v1.y - __half2float(b2));
            a = __float2half(v1.z); b2 = __float2half(v1.w);
            h1.y = pk2h(__half2float(a), __half2float(b2));
            l1.y = pk2h(v1.z - __half2float(a), v1.w - __half2float(b2));
            *(uint2*)(stg + o)                           = h0;
            *(uint2*)(stg + o + 64 * A_STRIDE)           = h1;
            *(uint2*)(stg + OFF_ALO + o)                 = l0;
            *(uint2*)(stg + OFF_ALO + o + 64 * A_STRIDE) = l1;
        };
        // ---- B cp.async (fp16 W), double-buffered ----
        const int br = tid >> 2;         // row 0..127 (and +128)
        const int bg = tid & 3;          // 16B group
        auto ldB = [&](int c, int s) {
            uint32_t d0 = sb + SM_B + s * B_STG + (uint32_t)(br * A_STRIDE + bg * 16);
            uint32_t d1 = d0 + 128 * A_STRIDE;
            const __half* s0 = &g_Wh[br * DD + c * KC + bg * 8];
            CP16(d0, s0);
            CP16(d1, s0 + 128 * DD);
        };

        float acc[2][8][4];
#pragma unroll
        for (int mt = 0; mt < 2; mt++)
#pragma unroll
            for (int nt = 0; nt < 8; nt++)
#pragma unroll
                for (int i = 0; i < 4; i++) acc[mt][nt][i] = 0.f;

        const uint32_t a_off = (uint32_t)((wm * 32 + (lane & 15)) * A_STRIDE + (lane >> 4) * 16);
        const uint32_t b_off = (uint32_t)((wn * 64 + (lane & 7) + ((lane >> 4) & 1) * 8) * A_STRIDE
                                          + ((lane >> 3) & 1) * 16);

        auto compute_half = [&](int c, int ks) {
            const uint32_t areg = sb + SM_TILES + c * A_CH_STRIDE;
            const uint32_t bstg = sb + SM_B + (c & 1) * B_STG;
            uint32_t ah[2][4], al[2][4];
#pragma unroll
            for (int mt = 0; mt < 2; mt++) {
                uint32_t ao = areg + a_off + mt * 16 * A_STRIDE + ks * 32;
                ldsm4(ah[mt], ao);
                ldsm4(al[mt], ao + OFF_ALO);
            }
#pragma unroll
            for (int p = 0; p < 4; p++) {
                uint32_t bh[4];
                ldsm4(bh, bstg + b_off + p * 16 * A_STRIDE + ks * 32);
#pragma unroll
                for (int mt = 0; mt < 2; mt++) {
                    mma_f16(acc[mt][2*p],   ah[mt], bh);
                    mma_f16(acc[mt][2*p],   al[mt], bh);
                    mma_f16(acc[mt][2*p+1], ah[mt], bh + 2);
                    mma_f16(acc[mt][2*p+1], al[mt], bh + 2);
                }
            }
        };

        // ---- prologue ----
        float4 va0, va1;
        ldA(0, va0, va1);
        ldB(0, 0); CP_COMMIT();
        stA(va0, va1, 0);
        ldA(1, va0, va1);
        CP_WAIT0();
        __syncthreads();

#pragma unroll 1
        for (int c = 0; c < NCH; c++) {
            const bool more = (c + 1) < NCH;
            if (more) { ldB(c + 1, (c + 1) & 1); CP_COMMIT(); }
            compute_half(c, 0);
            if (more) {
                stA(va0, va1, c + 1);                 // hides under ks=1 HMMAs
                if (c + 2 < NCH) ldA(c + 2, va0, va1);
            }
            compute_half(c, 1);
            if (more) { CP_WAIT0(); __syncthreads(); }
        }

        // ---- score epilogue: attn * tanh(z + bias), reduce over e ----
        const float* bsm = (const float*)(smem + SM_BIAS);
        const float* atm = (const float*)(smem + SM_ATTN);
        float sc[4] = {0.f, 0.f, 0.f, 0.f};
#pragma unroll
        for (int mt = 0; mt < 2; mt++)
#pragma unroll
            for (int nt = 0; nt < 8; nt++) {
                int e0 = wn * 64 + nt * 8 + 2 * (lane & 3);
                float b0 = bsm[e0], b1 = bsm[e0 + 1];
                float a0 = atm[e0], a1 = atm[e0 + 1];
                sc[mt*2+0] += a0 * tanhf(acc[mt][nt][0] + b0) + a1 * tanhf(acc[mt][nt][1] + b1);
                sc[mt*2+1] += a0 * tanhf(acc[mt][nt][2] + b0) + a1 * tanhf(acc[mt][nt][3] + b1);
            }
#pragma unroll
        for (int off = 1; off <= 2; off <<= 1)
#pragma unroll
            for (int i = 0; i < 4; i++)
                sc[i] += __shfl_xor_sync(0xffffffffu, sc[i], off);

        float* red = (float*)(smem + SM_RED);
        if ((lane & 3) == 0) {
            int r = wm * 32 + (lane >> 2);
            red[wn * 128 + r + 0]  = sc[0];
            red[wn * 128 + r + 8]  = sc[1];
            red[wn * 128 + r + 16] = sc[2];
            red[wn * 128 + r + 24] = sc[3];
        }
        __syncthreads();

        // ---- fused online-softmax stats epilogue ----
        float s_t = 0.f;
        int valid = 0;
        if (tid < 128) {
            s_t = red[tid] + red[128 + tid] + red[256 + tid] + red[384 + tid];
            valid = mask[m0 + tid];
        }
        float ml = (tid < 128 && valid) ? s_t : -3.0e38f;
#pragma unroll
        for (int off = 16; off >= 1; off >>= 1)
            ml = fmaxf(ml, __shfl_xor_sync(0xffffffffu, ml, off));
        float* mw = (float*)(smem + SM_BIAS);       // bias no longer needed
        if (lane == 0) mw[wid] = ml;
        __syncthreads();                            // all red[] reads done
        float mloc = mw[0];
#pragma unroll
        for (int i = 1; i < 16; i++) mloc = fmaxf(mloc, mw[i]);

        float* psh = (float*)(smem + SM_RED);
        float pz = 0.f;
        if (tid < 128) {
            pz = valid ? __expf(s_t - mloc) : 0.f;
            psh[tid] = pz;
        }
#pragma unroll
        for (int off = 16; off >= 1; off >>= 1)
            pz += __shfl_xor_sync(0xffffffffu, pz, off);
        float* zw = (float*)(smem + SM_ATTN);
        if (lane == 0) zw[wid] = pz;
        __syncthreads();

        // partial weighted stats from SMEM A tiles (x = hi + lo, err ~2^-22)
        const int q  = tid & 63;
        const int tg = tid >> 6;
        const char* ab = smem + SM_TILES + (q >> 3) * A_CH_STRIDE + (q & 7) * 8;
        float4 mu = {0.f,0.f,0.f,0.f}, m2 = {0.f,0.f,0.f,0.f};
#pragma unroll 4
        for (int t = tg; t < MT; t += 8) {
            float w = psh[t];
            uint2 hh = *(const uint2*)(ab + t * A_STRIDE);
            uint2 ll = *(const uint2*)(ab + t * A_STRIDE + OFF_ALO);
            float2 h0 = __half22float2(*(__half2*)&hh.x);
            float2 h1 = __half22float2(*(__half2*)&hh.y);
            float2 l0 = __half22float2(*(__half2*)&ll.x);
            float2 l1 = __half22float2(*(__half2*)&ll.y);
            float vx = h0.x + l0.x, vy = h0.y + l0.y;
            float vz = h1.x + l1.x, vw = h1.y + l1.y;
            mu.x += w*vx; mu.y += w*vy; mu.z += w*vz; mu.w += w*vw;
            m2.x += w*vx*vx; m2.y += w*vy*vy; m2.z += w*vz*vz; m2.w += w*vw*vw;
        }
        float4* bmu = (float4*)(smem + SM_B);       // B stages consumed
        float4* bm2 = bmu + 512;
        bmu[tid] = mu; bm2[tid] = m2;
        __syncthreads();
        if (tid < 64) {
            float4 omu = {0.f,0.f,0.f,0.f}, om2 = {0.f,0.f,0.f,0.f};
#pragma unroll
            for (int g = 0; g < 8; g++) {
                float4 a = bmu[g * 64 + q];
                omu.x += a.x; omu.y += a.y; omu.z += a.z; omu.w += a.w;
                float4 b2 = bm2[g * 64 + q];
                om2.x += b2.x; om2.y += b2.y; om2.z += b2.z; om2.w += b2.w;
            }
            ((float4*)&g_part[(blockIdx.x * 2) * DD])[q]     = omu;
            ((float4*)&g_part[(blockIdx.x * 2 + 1) * DD])[q] = om2;
        }
        if (tid == 0) {
            float Z = 0.f;
#pragma unroll
            for (int i = 0; i < 16; i++) Z += zw[i];
            g_meta[blockIdx.x * 2]     = mloc;
            g_meta[blockIdx.x * 2 + 1] = Z;
        }
    } else {
        if (tid == 0) {
            g_meta[blockIdx.x * 2]     = -3.0e38f;
            g_meta[blockIdx.x * 2 + 1] = 0.f;
        }
    }

    // ---- arrival; last CTA of this batch finalizes inline ----
    __threadfence();
    __syncthreads();
    if (tid == 0)
        *s_flag = (atomicAdd(&g_arr[bidx], 1) == CPB - 1) ? 1 : 0;
    __syncthreads();
    if (*s_flag) {
        __threadfence();
        if (tid < 256) {
            const int d = tid;
            float M = -3.0e38f;
#pragma unroll
            for (int c = 0; c < CPB; c++) {
                float zc = g_meta[(bidx * CPB + c) * 2 + 1];
                if (zc > 0.f) M = fmaxf(M, g_meta[(bidx * CPB + c) * 2]);
            }
            float Z = 0.f, muf = 0.f, m2f = 0.f;
#pragma unroll 1
            for (int c = 0; c < CPB; c++) {
                float zc = g_meta[(bidx * CPB + c) * 2 + 1];
                if (zc <= 0.f) continue;      // dead tile: partials never written
                float f = __expf(g_meta[(bidx * CPB + c) * 2] - M);
                Z   += f * zc;
                muf += f * g_part[((bidx * CPB + c) * 2) * DD + d];
                m2f += f * g_part[((bidx * CPB + c) * 2 + 1) * DD + d];
            }
            float inv = 1.f / Z;
            muf *= inv; m2f *= inv;
            float var = fmaxf(m2f - muf * muf, 1e-5f);
            out[bidx * 2 * DD + d]      = muf;
            out[bidx * 2 * DD + DD + d] = sqrtf(var);
        }
    }
}

// ---------------------------------------------------------------------------
extern "C" void kernel_launch(void* const* d_in, const int* in_sizes, int n_in,
                              void* d_out, int out_size)
{
    const float* xs   = (const float*)d_in[0];
    const int*   mask = (const int*)  d_in[1];
    // d_in[2] = mask2 (unused)
    const float* W    = (const float*)d_in[3];
    const float* bias = (const float*)d_in[4];
    const float* attn = (const float*)d_in[5];
    float* out = (float*)d_out;

    static int smem_set = 0;
    if (!smem_set) {
        cudaFuncSetAttribute(score_kernel, cudaFuncAttributeMaxDynamicSharedMemorySize, SMEM_BYTES);
        smem_set = 1;
    }

    prep_kernel<<<64, 256>>>(W);
    score_kernel<<<NCTA, 512, SMEM_BYTES>>>(xs, mask, bias, attn, out);
}

// round 17
// speedup vs baseline: 1.0907x; 1.0907x over previous
#include <cuda_runtime.h>
#include <cuda_fp16.h>
#include <math.h>
#include <stdint.h>

#define BB 64
#define TT 2048
#define DD 256
#define NN (BB*TT)

#define MT 64                  // frames per CTA (32 CTAs per batch row)
#define KC 32                  // K chunk (fp16)
#define NCH (DD/KC)            // 8 chunks
#define NCTA (NN/MT)           // 2048
#define CPB (TT/MT)            // 32 chunks per batch

// ---------------- device scratch (no allocations allowed) ------------------
__device__ float g_part[NCTA * 2 * DD];   // per-tile [P_mu | P_m2]
__device__ float g_meta[NCTA * 2];        // per-tile [m_loc, Z_loc]
__device__ __align__(16) __half g_Wh[DD * DD];   // W rounded to fp16

// ---------------- smem layout (dynamic), bytes -----------------------------
#define SM_BIAS   0             // 256 f  (reused as mw scratch post-GEMM)
#define SM_ATTN   1024          // 256 f  (reused as zw scratch post-GEMM)
#define SM_RED    2048          // 256 f  (score red, then p[] weights)
#define SM_A      4096          // A double buffer: 2 stages x 10240
#define A_STRIDE  80            // 32 fp16 padded: stride/16 odd -> ldmatrix conflict-free
#define OFF_ALO   5120          // lo plane within an A stage (64 rows x 80B)
#define A_STG     10240
#define SM_B      (SM_A + 2*A_STG)       // 24576; B double buffer: 2 x 20480
#define B_STG     20480
#define SMEM_BYTES (SM_B + 2*B_STG)      // 65536 -> 2 CTAs/SM

// ---------------- PTX helpers (baseline ISA only: sm_80-class) -------------
__device__ __forceinline__ uint32_t smem_u32(const void* p) {
    uint32_t a;
    asm("{ .reg .u64 t; cvta.to.shared.u64 t, %1; cvt.u32.u64 %0, t; }" : "=r"(a) : "l"(p));
    return a;
}
__device__ __forceinline__ void ldsm4(uint32_t* r, uint32_t addr) {
    asm volatile("ldmatrix.sync.aligned.m8n8.x4.shared.b16 {%0,%1,%2,%3}, [%4];"
                 : "=r"(r[0]), "=r"(r[1]), "=r"(r[2]), "=r"(r[3]) : "r"(addr));
}
__device__ __forceinline__ void mma_f16(float* d, const uint32_t* a, const uint32_t* b) {
    asm volatile("mma.sync.aligned.m16n8k16.row.col.f32.f16.f16.f32 "
                 "{%0,%1,%2,%3}, {%4,%5,%6,%7}, {%8,%9}, {%0,%1,%2,%3};"
                 : "+f"(d[0]), "+f"(d[1]), "+f"(d[2]), "+f"(d[3])
                 : "r"(a[0]), "r"(a[1]), "r"(a[2]), "r"(a[3]), "r"(b[0]), "r"(b[1]));
}
#define CP16(dst, src) asm volatile("cp.async.cg.shared.global [%0], [%1], 16;" :: "r"(dst), "l"(src))
#define CP_COMMIT()    asm volatile("cp.async.commit_group;" ::: "memory")
#define CP_WAIT0()     asm volatile("cp.async.wait_group 0;" ::: "memory")

__device__ __forceinline__ uint32_t pk2h(float a, float b) {
    __half2 h = __floats2half2_rn(a, b);
    return *(uint32_t*)&h;
}

// ---------------------------------------------------------------------------
// Kernel 0: round W to fp16 (float4 vectorized).
// ---------------------------------------------------------------------------
__global__ void prep_kernel(const float* __restrict__ W)
{
    int i = blockIdx.x * blockDim.x + threadIdx.x;   // 16384 float4 units
    float4 w = ((const float4*)W)[i];
    uint2 hp;
    hp.x = pk2h(w.x, w.y);
    hp.y = pk2h(w.z, w.w);
    ((uint2*)g_Wh)[i] = hp;
}

// ---------------------------------------------------------------------------
// Kernel 1: fp16 2-term split GEMM on mma.sync (z = Ah*Wh + Al*Wh) + fused
// online-softmax stats. M=64 x N=256 per CTA, 256 thr / 8 warps, 2 CTAs/SM.
// PREFIX-MASK SKIP for dead tiles.
// ---------------------------------------------------------------------------
__global__ __launch_bounds__(256, 2)
void score_kernel(const float* __restrict__ x, const int* __restrict__ mask,
                  const float* __restrict__ bias, const float* __restrict__ attn)
{
    const long m0 = (long)blockIdx.x * MT;

    if (mask[m0] == 0) {
        if (threadIdx.x == 0) {
            g_meta[blockIdx.x * 2]     = -3.0e38f;
            g_meta[blockIdx.x * 2 + 1] = 0.f;
        }
        return;
    }

    extern __shared__ char smem[];
    const uint32_t sb = smem_u32(smem);
    const int tid = threadIdx.x;
    const int lane = tid & 31;
    const int wid = tid >> 5;
    const int wm = wid & 1;          // M half (32 rows)
    const int wn = wid >> 1;         // N quarter (64 cols)

    ((float*)(smem + SM_BIAS))[tid] = bias[tid];
    ((float*)(smem + SM_ATTN))[tid] = attn[tid];

    // ---- A global load / exact fp16 hi+lo split + store ----
    const int ar  = tid >> 3;        // row 0..31 (and +32)
    const int ag  = tid & 7;         // float4 group
    auto ldA = [&](int c, float4& v0, float4& v1) {
        const float* p = &x[(m0 + ar) * DD + c * KC + ag * 4];
        v0 = *(const float4*)p;
        v1 = *(const float4*)(p + 32 * DD);
    };
    auto stA = [&](float4 v0, float4 v1, int s) {
        char* stg = smem + SM_A + s * A_STG;
        uint32_t o = (uint32_t)(ar * A_STRIDE + ag * 8);
        uint2 h0, h1, l0, l1;
        __half a, b2;
        a = __float2half(v0.x); b2 = __float2half(v0.y);
        h0.x = pk2h(__half2float(a), __half2float(b2));
        l0.x = pk2h(v0.x - __half2float(a), v0.y - __half2float(b2));
        a = __float2half(v0.z); b2 = __float2half(v0.w);
        h0.y = pk2h(__half2float(a), __half2float(b2));
        l0.y = pk2h(v0.z - __half2float(a), v0.w - __half2float(b2));
        a = __float2half(v1.x); b2 = __float2half(v1.y);
        h1.x = pk2h(__half2float(a), __half2float(b2));
        l1.x = pk2h(v1.x - __half2float(a), v1.y - __half2float(b2));
        a = __float2half(v1.z); b2 = __float2half(v1.w);
        h1.y = pk2h(__half2float(a), __half2float(b2));
        l1.y = pk2h(v1.z - __half2float(a), v1.w - __half2float(b2));
        *(uint2*)(stg + o)                           = h0;
        *(uint2*)(stg + o + 32 * A_STRIDE)           = h1;
        *(uint2*)(stg + OFF_ALO + o)                 = l0;
        *(uint2*)(stg + OFF_ALO + o + 32 * A_STRIDE) = l1;
    };
    // ---- B cp.async (fp16 W), double-buffered: 4 x 16B per thread ----
    auto ldB = [&](int c, int s) {
        uint32_t base = sb + SM_B + s * B_STG;
#pragma unroll
        for (int i = 0; i < 4; i++) {
            int u = tid + 256 * i;           // 1024 16B-groups
            int row = u >> 2, g = u & 3;
            CP16(base + (uint32_t)(row * A_STRIDE + g * 16),
                 &g_Wh[row * DD + c * KC + g * 8]);
        }
    };

    float acc[2][8][4];
#pragma unroll
    for (int mt = 0; mt < 2; mt++)
#pragma unroll
        for (int nt = 0; nt < 8; nt++)
#pragma unroll
            for (int i = 0; i < 4; i++) acc[mt][nt][i] = 0.f;

    const uint32_t a_off = (uint32_t)((wm * 32 + (lane & 15)) * A_STRIDE + (lane >> 4) * 16);
    const uint32_t b_off = (uint32_t)((wn * 64 + (lane & 7) + ((lane >> 4) & 1) * 8) * A_STRIDE
                                      + ((lane >> 3) & 1) * 16);

    auto compute_half = [&](int c, int ks) {
        const uint32_t astg = sb + SM_A + (c & 1) * A_STG;
        const uint32_t bstg = sb + SM_B + (c & 1) * B_STG;
        uint32_t ah[2][4], al[2][4];
#pragma unroll
        for (int mt = 0; mt < 2; mt++) {
            uint32_t ao = astg + a_off + mt * 16 * A_STRIDE + ks * 32;
            ldsm4(ah[mt], ao);
            ldsm4(al[mt], ao + OFF_ALO);
        }
#pragma unroll
        for (int p = 0; p < 4; p++) {
            uint32_t bh[4];
            ldsm4(bh, bstg + b_off + p * 16 * A_STRIDE + ks * 32);
#pragma unroll
            for (int mt = 0; mt < 2; mt++) {
                mma_f16(acc[mt][2*p],   ah[mt], bh);
                mma_f16(acc[mt][2*p],   al[mt], bh);
                mma_f16(acc[mt][2*p+1], ah[mt], bh + 2);
                mma_f16(acc[mt][2*p+1], al[mt], bh + 2);
            }
        }
    };

    // ---- prologue ----
    float4 va0, va1;
    ldA(0, va0, va1);
    ldB(0, 0); CP_COMMIT();
    stA(va0, va1, 0);
    ldA(1, va0, va1);
    CP_WAIT0();
    __syncthreads();

#pragma unroll 1
    for (int c = 0; c < NCH; c++) {
        const bool more = (c + 1) < NCH;
        if (more) { ldB(c + 1, (c + 1) & 1); CP_COMMIT(); }
        compute_half(c, 0);
        if (more) {
            stA(va0, va1, (c + 1) & 1);          // hides under ks=1 HMMAs
            if (c + 2 < NCH) ldA(c + 2, va0, va1);
        }
        compute_half(c, 1);
        if (more) { CP_WAIT0(); __syncthreads(); }
    }

    // ---- score epilogue: attn * tanh(z + bias), reduce over e ----
    const float* bsm = (const float*)(smem + SM_BIAS);
    const float* atm = (const float*)(smem + SM_ATTN);
    float sc[4] = {0.f, 0.f, 0.f, 0.f};
#pragma unroll
    for (int mt = 0; mt < 2; mt++)
#pragma unroll
        for (int nt = 0; nt < 8; nt++) {
            int e0 = wn * 64 + nt * 8 + 2 * (lane & 3);
            float b0 = bsm[e0], b1 = bsm[e0 + 1];
            float a0 = atm[e0], a1 = atm[e0 + 1];
            sc[mt*2+0] += a0 * tanhf(acc[mt][nt][0] + b0) + a1 * tanhf(acc[mt][nt][1] + b1);
            sc[mt*2+1] += a0 * tanhf(acc[mt][nt][2] + b0) + a1 * tanhf(acc[mt][nt][3] + b1);
        }
#pragma unroll
    for (int off = 1; off <= 2; off <<= 1)
#pragma unroll
        for (int i = 0; i < 4; i++)
            sc[i] += __shfl_xor_sync(0xffffffffu, sc[i], off);

    float* red = (float*)(smem + SM_RED);
    __syncthreads();
    if ((lane & 3) == 0) {
        int r = wm * 32 + (lane >> 2);
        red[wn * 64 + r + 0]  = sc[0];    // mt0 rows r+0
        red[wn * 64 + r + 8]  = sc[1];    // mt0 rows r+8
        red[wn * 64 + r + 16] = sc[2];    // mt1 rows r+16
        red[wn * 64 + r + 24] = sc[3];    // mt1 rows r+24
    }
    __syncthreads();

    // ---- fused online-softmax stats epilogue (64 frames) ----
    float s_t = 0.f;
    int valid = 0;
    if (tid < 64) {
        s_t = red[tid] + red[64 + tid] + red[128 + tid] + red[192 + tid];
        valid = mask[m0 + tid];
    }
    float ml = (tid < 64 && valid) ? s_t : -3.0e38f;
#pragma unroll
    for (int off = 16; off >= 1; off >>= 1)
        ml = fmaxf(ml, __shfl_xor_sync(0xffffffffu, ml, off));
    float* mw = (float*)(smem + SM_BIAS);       // bias no longer needed
    if (lane == 0) mw[wid] = ml;
    __syncthreads();                            // all red[] reads done
    float mloc = mw[0];
#pragma unroll
    for (int i = 1; i < 8; i++) mloc = fmaxf(mloc, mw[i]);

    float* psh = (float*)(smem + SM_RED);
    float pz = 0.f;
    if (tid < 64) {
        pz = valid ? __expf(s_t - mloc) : 0.f;
        psh[tid] = pz;
    }
#pragma unroll
    for (int off = 16; off >= 1; off >>= 1)
        pz += __shfl_xor_sync(0xffffffffu, pz, off);
    float* zw = (float*)(smem + SM_ATTN);
    if (lane == 0) zw[wid] = pz;
    __syncthreads();

    // ---- partial weighted stats (x from global, L2-warm) ----
    const int q  = tid & 63;
    const int tg = tid >> 6;                 // 0..3
    const float4* xb = (const float4*)(x + m0 * DD) + q;
    float4 mu = {0.f,0.f,0.f,0.f}, m2 = {0.f,0.f,0.f,0.f};
#pragma unroll 4
    for (int t = tg; t < MT; t += 4) {
        float w = psh[t];
        float4 v = xb[(long)t * 64];
        mu.x += w*v.x; mu.y += w*v.y; mu.z += w*v.z; mu.w += w*v.w;
        m2.x += w*v.x*v.x; m2.y += w*v.y*v.y; m2.z += w*v.z*v.z; m2.w += w*v.w*v.w;
    }
    float4* bmu = (float4*)(smem + SM_A);       // A stages consumed
    float4* bm2 = bmu + 256;
    bmu[tid] = mu; bm2[tid] = m2;
    __syncthreads();
    if (tid < 64) {
        float4 omu = {0.f,0.f,0.f,0.f}, om2 = {0.f,0.f,0.f,0.f};
#pragma unroll
        for (int g = 0; g < 4; g++) {
            float4 a = bmu[g * 64 + q];
            omu.x += a.x; omu.y += a.y; omu.z += a.z; omu.w += a.w;
            float4 b2 = bm2[g * 64 + q];
            om2.x += b2.x; om2.y += b2.y; om2.z += b2.z; om2.w += b2.w;
        }
        ((float4*)&g_part[(blockIdx.x * 2) * DD])[q]     = omu;
        ((float4*)&g_part[(blockIdx.x * 2 + 1) * DD])[q] = om2;
    }
    if (tid == 0) {
        float Z = 0.f;
#pragma unroll
        for (int i = 0; i < 8; i++) Z += zw[i];
        g_meta[blockIdx.x * 2]     = mloc;
        g_meta[blockIdx.x * 2 + 1] = Z;
    }
}

// ---------------------------------------------------------------------------
// Kernel 2: finalize — merge chunk-partials per batch (online softmax),
// skipping dead chunks (Z == 0); compute mu / sqrt(var), write out.
// ---------------------------------------------------------------------------
__global__ __launch_bounds__(256)
void finalize_kernel(float* __restrict__ out)
{
    __shared__ float msh[CPB], zsh[CPB];
    const int b = blockIdx.x;
    const int d = threadIdx.x;
    if (d < CPB) {
        msh[d] = g_meta[(b * CPB + d) * 2];
        zsh[d] = g_meta[(b * CPB + d) * 2 + 1];
    }
    __syncthreads();

    float M = -3.0e38f;
#pragma unroll
    for (int c = 0; c < CPB; c++)
        if (zsh[c] > 0.f) M = fmaxf(M, msh[c]);

    float Z = 0.f, mu = 0.f, m2 = 0.f;
#pragma unroll 1
    for (int c = 0; c < CPB; c++) {
        if (zsh[c] <= 0.f) continue;      // dead tile: partials never written
        float f = __expf(msh[c] - M);
        Z  += f * zsh[c];
        mu += f * g_part[((b * CPB + c) * 2) * DD + d];
        m2 += f * g_part[((b * CPB + c) * 2 + 1) * DD + d];
    }
    float inv = 1.f / Z;
    mu *= inv; m2 *= inv;
    float var = fmaxf(m2 - mu * mu, 1e-5f);
    out[b * 2 * DD + d]      = mu;
    out[b * 2 * DD + DD + d] = sqrtf(var);
}

// ---------------------------------------------------------------------------
extern "C" void kernel_launch(void* const* d_in, const int* in_sizes, int n_in,
                              void* d_out, int out_size)
{
    const float* xs   = (const float*)d_in[0];
    const int*   mask = (const int*)  d_in[1];
    // d_in[2] = mask2 (unused)
    const float* W    = (const float*)d_in[3];
    const float* bias = (const float*)d_in[4];
    const float* attn = (const float*)d_in[5];
    float* out = (float*)d_out;

    static int smem_set = 0;
    if (!smem_set) {
        cudaFuncSetAttribute(score_kernel, cudaFuncAttributeMaxDynamicSharedMemorySize, SMEM_BYTES);
        smem_set = 1;
    }

    prep_kernel<<<64, 256>>>(W);
    score_kernel<<<NCTA, 256, SMEM_BYTES>>>(xs, mask, bias, attn);
    finalize_kernel<<<BB, 256>>>(out);
}